// round 1
// baseline (speedup 1.0000x reference)
#include <cuda_runtime.h>
#include <math.h>

#define BB 8
#define NN 2048
#define IND 128
#define OUTD 64
#define NEG_SLOPE 0.2f

// ---------------- scratch (static device globals; no allocations) ----------------
__device__ float g_hp[BB * NN * OUTD];        // projected features (4 MB)
__device__ float g_s[BB * NN];                // s_i = hp . a_src
__device__ float g_d[BB * NN];                // d_j = hp . a_dst
__device__ float g_sortedD[BB * NN];          // per-batch ascending d
__device__ int   g_sortIdx[BB * NN];
__device__ float g_w[2 * BB * 65 * NN];       // [branch][b][dim][r] weighted sorted payloads (8.5 MB)
__device__ float g_tab[(size_t)BB * 2049 * 130]; // [b][k][0..64]=sufPos, [65..129]=prefNeg (8.5 MB)

// ---------------- kernel 1: hp = h @ W_fc + b_fc ----------------
// block: 256 threads handles 32 rows x 64 cols. smem: 16KB h-tile + 32KB W = 48KB.
__global__ void projectK(const float* __restrict__ h, const float* __restrict__ W,
                         const float* __restrict__ bfc) {
    __shared__ float sH[32 * IND];
    __shared__ float sW[IND * OUTD];
    const int t = threadIdx.x;
    const int blockRow = blockIdx.x * 32;

    for (int i = t; i < IND * OUTD; i += 256) sW[i] = W[i];
    const float* hbase = h + (size_t)blockRow * IND;
    for (int i = t; i < 32 * IND; i += 256) sH[i] = hbase[i];
    __syncthreads();

    const int dcol = t & 63;
    const int rg = t >> 6;  // 0..3, each covers 8 rows
    float acc[8];
    const float bv = bfc[dcol];
#pragma unroll
    for (int r = 0; r < 8; r++) acc[r] = bv;

#pragma unroll 4
    for (int k = 0; k < IND; k++) {
        const float wv = sW[k * OUTD + dcol];
#pragma unroll
        for (int r = 0; r < 8; r++)
            acc[r] = fmaf(sH[(rg * 8 + r) * IND + k], wv, acc[r]);
    }
    float* out = g_hp + (size_t)blockRow * OUTD;
#pragma unroll
    for (int r = 0; r < 8; r++) out[(size_t)(rg * 8 + r) * OUTD + dcol] = acc[r];
}

// ---------------- kernel 2: s_i = hp.a_src ; d_i = hp.a_dst ----------------
__global__ void sdK(const float* __restrict__ asrc, const float* __restrict__ adst) {
    const int row = blockIdx.x;
    const int t = threadIdx.x;  // 64
    const float v = g_hp[(size_t)row * OUTD + t];
    float sv = v * asrc[t];
    float dv = v * adst[t];
#pragma unroll
    for (int o = 16; o > 0; o >>= 1) {
        sv += __shfl_down_sync(0xffffffffu, sv, o);
        dv += __shfl_down_sync(0xffffffffu, dv, o);
    }
    __shared__ float ss[2], sd_[2];
    const int w = t >> 5;
    if ((t & 31) == 0) { ss[w] = sv; sd_[w] = dv; }
    __syncthreads();
    if (t == 0) {
        g_s[row] = ss[0] + ss[1];
        g_d[row] = sd_[0] + sd_[1];
    }
}

// ---------------- kernel 3: per-batch bitonic sort of d (ascending, with index) ----------------
__global__ void sortK() {
    const int b = blockIdx.x;
    __shared__ float key[NN];
    __shared__ int idx[NN];
    const int t = threadIdx.x;  // 1024

    for (int i = t; i < NN; i += 1024) { key[i] = g_d[b * NN + i]; idx[i] = i; }
    __syncthreads();

    for (int k = 2; k <= NN; k <<= 1) {
        for (int j = k >> 1; j > 0; j >>= 1) {
            for (int i = t; i < NN; i += 1024) {
                const int ixj = i ^ j;
                if (ixj > i) {
                    const bool up = ((i & k) == 0);
                    const float a = key[i], c = key[ixj];
                    const bool swap = up ? (a > c) : (a < c);
                    if (swap) {
                        key[i] = c; key[ixj] = a;
                        const int ia = idx[i]; idx[i] = idx[ixj]; idx[ixj] = ia;
                    }
                }
            }
            __syncthreads();
        }
    }
    for (int i = t; i < NN; i += 1024) {
        g_sortedD[b * NN + i] = key[i];
        g_sortIdx[b * NN + i] = idx[i];
    }
}

// ---------------- kernel 4: build weighted payloads in sorted order, [branch][b][dim][r] ----------------
// warp lanes = 32 consecutive sorted positions r; loop over 65 dims (hp gather amortized by L1).
__global__ void permuteK() {
    const int b = blockIdx.x >> 3;
    const int warpInB = ((blockIdx.x & 7) << 3) + (threadIdx.x >> 5);
    const int lane = threadIdx.x & 31;
    const int r = warpInB * 32 + lane;

    const float dv = g_sortedD[b * NN + r];
    const int j = g_sortIdx[b * NN + r];
    const float p = __expf(dv);              // positive-branch weight
    const float q = __expf(NEG_SLOPE * dv);  // negative-branch weight

    const float* hprow = g_hp + ((size_t)b * NN + j) * OUTD;
    float* wp = g_w + (((size_t)0 * BB + b) * 65) * NN;  // pos branch
    float* wn = g_w + (((size_t)1 * BB + b) * 65) * NN;  // neg branch
#pragma unroll 8
    for (int dim = 0; dim < OUTD; dim++) {
        const float hv = hprow[dim];
        wp[(size_t)dim * NN + r] = p * hv;
        wn[(size_t)dim * NN + r] = q * hv;
    }
    wp[(size_t)64 * NN + r] = p;
    wn[(size_t)64 * NN + r] = q;
}

// ---------------- kernel 5: scans -> g_tab ----------------
// branch 0 (pos): suffix sums sufPos[k] = sum_{r>=k} -> tab[b][k][dim]
// branch 1 (neg): exclusive prefix prefNeg[k] = sum_{r<k} -> tab[b][k][65+dim]
__global__ void scanK() {
    const int blk = blockIdx.x;              // 0..1039
    const int branch = blk / (BB * 65);      // 0 = pos(suffix), 1 = neg(prefix)
    const int rest = blk - branch * BB * 65;
    const int b = rest / 65;
    const int dim = rest % 65;

    const float* src = g_w + (((size_t)branch * BB + b) * 65 + dim) * NN;
    const int t = threadIdx.x;               // 256, each owns 8 consecutive elements
    const int lane = t & 31, warp = t >> 5;

    float v[8];
    const float* pp = src + t * 8;
#pragma unroll
    for (int e = 0; e < 8; e++) v[e] = pp[e];

    float tot;
    if (branch == 1) {                       // forward inclusive within chunk
#pragma unroll
        for (int e = 1; e < 8; e++) v[e] += v[e - 1];
        tot = v[7];
    } else {                                 // backward inclusive (suffix) within chunk
#pragma unroll
        for (int e = 6; e >= 0; e--) v[e] += v[e + 1];
        tot = v[0];
    }

    __shared__ float wtot[8];
    float x = tot;
    if (branch == 1) {
#pragma unroll
        for (int o = 1; o < 32; o <<= 1) {
            const float y = __shfl_up_sync(0xffffffffu, x, o);
            if (lane >= o) x += y;
        }
        if (lane == 31) wtot[warp] = x;
    } else {
#pragma unroll
        for (int o = 1; o < 32; o <<= 1) {
            const float y = __shfl_down_sync(0xffffffffu, x, o);
            if (lane < 32 - o) x += y;
        }
        if (lane == 0) wtot[warp] = x;
    }
    __syncthreads();

    float off = 0.f;
    if (branch == 1) { for (int w2 = 0; w2 < warp; w2++) off += wtot[w2]; }
    else             { for (int w2 = warp + 1; w2 < 8; w2++) off += wtot[w2]; }
    const float base = off + x - tot;        // sum strictly outside this chunk (before/after)

    if (branch == 1) {
#pragma unroll
        for (int e = 0; e < 8; e++) {
            const int k = t * 8 + e + 1;     // prefNeg[k] = inclusive prefix through element k-1
            g_tab[((size_t)b * 2049 + k) * 130 + 65 + dim] = base + v[e];
        }
        if (t == 0) g_tab[((size_t)b * 2049 + 0) * 130 + 65 + dim] = 0.f;
    } else {
#pragma unroll
        for (int e = 0; e < 8; e++) {
            const int k = t * 8 + e;         // sufPos[k] = suffix from element k
            g_tab[((size_t)b * 2049 + k) * 130 + dim] = base + v[e];
        }
        if (t == 0) g_tab[((size_t)b * 2049 + 2048) * 130 + dim] = 0.f;
    }
}

// ---------------- kernel 6: per-row output ----------------
// warp per row: binary search threshold in sorted d, combine branch tables, softmax-ratio, ELU.
__global__ void outK(const float* __restrict__ battn, float* __restrict__ out) {
    const int row = blockIdx.x * 8 + (threadIdx.x >> 5);
    const int lane = threadIdx.x & 31;
    const int b = row >> 11;  // NN = 2048 = 2^11

    const float ba = *battn;
    const float si = g_s[row] + ba;
    const float tt = -si;     // threshold: d_j >= tt -> positive branch

    const float* sd = g_sortedD + b * NN;
    int lo = 0, hi = NN;
    while (lo < hi) {
        const int mid = (lo + hi) >> 1;
        if (sd[mid] < tt) lo = mid + 1; else hi = mid;
    }

    const float* tb = g_tab + ((size_t)b * 2049 + lo) * 130;
    const float P = __expf(si);
    const float Q = __expf(NEG_SLOPE * si);
    const float den = fmaf(P, tb[64], Q * tb[129]);
    const float inv = 1.0f / den;

    float* orow = out + (size_t)row * OUTD;
#pragma unroll
    for (int d0 = 0; d0 < 2; d0++) {
        const int d = lane + d0 * 32;
        const float num = fmaf(P, tb[d], Q * tb[65 + d]);
        const float o = num * inv;
        orow[d] = (o > 0.f) ? o : expm1f(o);  // ELU (alpha=1)
    }
}

// ---------------- launch ----------------
extern "C" void kernel_launch(void* const* d_in, const int* in_sizes, int n_in,
                              void* d_out, int out_size) {
    const float* h     = (const float*)d_in[0];
    const float* W     = (const float*)d_in[1];
    const float* bfc   = (const float*)d_in[2];
    const float* asrc  = (const float*)d_in[3];
    const float* adst  = (const float*)d_in[4];
    const float* battn = (const float*)d_in[5];
    float* out = (float*)d_out;

    projectK<<<(BB * NN) / 32, 256>>>(h, W, bfc);
    sdK<<<BB * NN, 64>>>(asrc, adst);
    sortK<<<BB, 1024>>>();
    permuteK<<<64, 256>>>();
    scanK<<<2 * BB * 65, 256>>>();
    outK<<<(BB * NN) / 8, 256>>>(battn, out);
}

// round 2
// speedup vs baseline: 1.5628x; 1.5628x over previous
#include <cuda_runtime.h>
#include <math.h>

#define BB 8
#define NN 2048
#define IND 128
#define OUTD 64
#define NEG_SLOPE 0.2f

// ---------------- scratch (static device globals; no allocations) ----------------
__device__ float g_hp[BB * NN * OUTD];        // projected features (4 MB)
__device__ float g_s[BB * NN];                // s_i = hp . a_src
__device__ float g_d[BB * NN];                // d_j = hp . a_dst
__device__ float g_sortedD[BB * NN];          // per-batch ascending d
__device__ int   g_sortIdx[BB * NN];
__device__ float g_wp[BB * NN];               // exp(d) at sorted position
__device__ float g_wq[BB * NN];               // exp(0.2 d) at sorted position
__device__ float g_tab[(size_t)BB * 2049 * 130]; // [b][k][0..64]=sufPos, [65..129]=prefNeg

// ---------------- kernel 1: hp = h @ W_fc + b_fc ----------------
// 64 rows x 64 cols per block; 256 threads = 16 col-quads x 16 row-groups(4 rows).
// Dynamic smem 64KB: sH[64][128] + sW[128][64]. All LDS are conflict-free float4.
__global__ void projectK(const float* __restrict__ h, const float* __restrict__ W,
                         const float* __restrict__ bfc) {
    extern __shared__ float sm[];
    float* sH = sm;                 // [64][128]
    float* sW = sm + 64 * IND;      // [128][64]
    const int t = threadIdx.x;
    const int rowBase = blockIdx.x * 64;

    const float4* hsrc = (const float4*)(h + (size_t)rowBase * IND);
    float4* sH4 = (float4*)sH;
#pragma unroll
    for (int i = t; i < 64 * IND / 4; i += 256) sH4[i] = hsrc[i];
    const float4* wsrc = (const float4*)W;
    float4* sW4 = (float4*)sW;
#pragma unroll
    for (int i = t; i < IND * OUTD / 4; i += 256) sW4[i] = wsrc[i];
    __syncthreads();

    const int q = t & 15;     // col quad: cols 4q..4q+3
    const int g = t >> 4;     // row group: rows 4g..4g+3
    const int c0 = q * 4;
    const int r0 = g * 4;

    const float4 b4 = *(const float4*)(bfc + c0);
    float acc[4][4];
#pragma unroll
    for (int r = 0; r < 4; r++) {
        acc[r][0] = b4.x; acc[r][1] = b4.y; acc[r][2] = b4.z; acc[r][3] = b4.w;
    }

    for (int k = 0; k < IND; k += 4) {
        float hv[4][4], wv[4][4];
#pragma unroll
        for (int r = 0; r < 4; r++) {
            const float4 a = *(const float4*)&sH[(r0 + r) * IND + k];
            hv[r][0] = a.x; hv[r][1] = a.y; hv[r][2] = a.z; hv[r][3] = a.w;
        }
#pragma unroll
        for (int kk = 0; kk < 4; kk++) {
            const float4 w = *(const float4*)&sW[(k + kk) * OUTD + c0];
            wv[kk][0] = w.x; wv[kk][1] = w.y; wv[kk][2] = w.z; wv[kk][3] = w.w;
        }
#pragma unroll
        for (int kk = 0; kk < 4; kk++)
#pragma unroll
            for (int r = 0; r < 4; r++)
#pragma unroll
                for (int c = 0; c < 4; c++)
                    acc[r][c] = fmaf(hv[r][kk], wv[kk][c], acc[r][c]);
    }

    float* outp = g_hp + (size_t)rowBase * OUTD;
#pragma unroll
    for (int r = 0; r < 4; r++) {
        float4 o; o.x = acc[r][0]; o.y = acc[r][1]; o.z = acc[r][2]; o.w = acc[r][3];
        *(float4*)&outp[(size_t)(r0 + r) * OUTD + c0] = o;
    }
}

// ---------------- kernel 2: s_i = hp.a_src ; d_i = hp.a_dst (warp per row) ----------------
__global__ void sdK(const float* __restrict__ asrc, const float* __restrict__ adst) {
    const int row = (blockIdx.x * blockDim.x + threadIdx.x) >> 5;
    const int lane = threadIdx.x & 31;
    const float2 v  = *(const float2*)(g_hp + (size_t)row * OUTD + lane * 2);
    const float2 as = *(const float2*)(asrc + lane * 2);
    const float2 ad = *(const float2*)(adst + lane * 2);
    float sv = fmaf(v.x, as.x, v.y * as.y);
    float dv = fmaf(v.x, ad.x, v.y * ad.y);
#pragma unroll
    for (int o = 16; o > 0; o >>= 1) {
        sv += __shfl_xor_sync(0xffffffffu, sv, o);
        dv += __shfl_xor_sync(0xffffffffu, dv, o);
    }
    if (lane == 0) { g_s[row] = sv; g_d[row] = dv; }
}

// ---------------- kernel 3: per-batch bitonic sort, packed 64-bit (key|idx) ----------------
__global__ void sortK() {
    const int b = blockIdx.x;
    __shared__ unsigned long long su[NN];
    const int t = threadIdx.x;  // 1024

    for (int i = t; i < NN; i += 1024) {
        const unsigned bits = __float_as_uint(g_d[b * NN + i]);
        const unsigned key = bits ^ ((bits & 0x80000000u) ? 0xFFFFFFFFu : 0x80000000u);
        su[i] = ((unsigned long long)key << 32) | (unsigned)i;
    }
    __syncthreads();

    for (int k = 2; k <= NN; k <<= 1) {
        for (int j = k >> 1; j > 0; j >>= 1) {
            const int i = ((t & ~(j - 1)) << 1) | (t & (j - 1));
            const int partner = i | j;
            const bool up = ((i & k) == 0);
            const unsigned long long A = su[i], B = su[partner];
            const unsigned long long lo_ = (A < B) ? A : B;
            const unsigned long long hi_ = (A < B) ? B : A;
            su[i] = up ? lo_ : hi_;
            su[partner] = up ? hi_ : lo_;
            if (j >= 64) __syncthreads(); else __syncwarp();
        }
        __syncthreads();  // warp-local writes must be visible before next k's cross-warp phase
    }

    for (int i = t; i < NN; i += 1024) {
        const unsigned long long u = su[i];
        const unsigned key = (unsigned)(u >> 32);
        const unsigned bits = key ^ ((key & 0x80000000u) ? 0x80000000u : 0xFFFFFFFFu);
        const float dv = __uint_as_float(bits);
        g_sortedD[b * NN + i] = dv;
        g_sortIdx[b * NN + i] = (int)(u & 0xFFFFFFFFu);
        g_wp[b * NN + i] = __expf(dv);
        g_wq[b * NN + i] = __expf(NEG_SLOPE * dv);
    }
}

// ---------------- kernel 4: fused gather + dual scan -> g_tab ----------------
// block = (b, dim). Gathers hp once, computes pos-suffix AND neg-prefix scans.
__global__ void scanK() {
    const int blk = blockIdx.x;          // 0..519
    const int b = blk / 65;
    const int dim = blk % 65;
    const int t = threadIdx.x;           // 256, each owns 8 consecutive r
    const int lane = t & 31, warp = t >> 5;
    const int base = b * NN;

    float vp[8], vn[8];
#pragma unroll
    for (int e = 0; e < 8; e++) {
        const int r = t * 8 + e;
        const float wpv = g_wp[base + r];
        const float wqv = g_wq[base + r];
        float val = 1.0f;
        if (dim < 64) {
            const int j = g_sortIdx[base + r];
            val = g_hp[((size_t)base + j) * OUTD + dim];
        }
        vp[e] = wpv * val;
        vn[e] = wqv * val;
    }

    // neg: forward inclusive within chunk; pos: backward inclusive (suffix)
#pragma unroll
    for (int e = 1; e < 8; e++) vn[e] += vn[e - 1];
#pragma unroll
    for (int e = 6; e >= 0; e--) vp[e] += vp[e + 1];
    const float totn = vn[7], totp = vp[0];

    __shared__ float wtn[8], wtp[8];
    float xn = totn, xp = totp;
#pragma unroll
    for (int o = 1; o < 32; o <<= 1) {
        const float yn = __shfl_up_sync(0xffffffffu, xn, o);
        if (lane >= o) xn += yn;
        const float yp = __shfl_down_sync(0xffffffffu, xp, o);
        if (lane < 32 - o) xp += yp;
    }
    if (lane == 31) wtn[warp] = xn;
    if (lane == 0)  wtp[warp] = xp;
    __syncthreads();

    float offn = 0.f, offp = 0.f;
    for (int w2 = 0; w2 < warp; w2++) offn += wtn[w2];
    for (int w2 = warp + 1; w2 < 8; w2++) offp += wtp[w2];
    const float basen = offn + xn - totn;   // sum strictly before this chunk
    const float basep = offp + xp - totp;   // sum strictly after this chunk

    float* tabb = g_tab + (size_t)b * 2049 * 130;
#pragma unroll
    for (int e = 0; e < 8; e++) {
        const int kp = t * 8 + e;
        tabb[(size_t)kp * 130 + dim] = basep + vp[e];              // sufPos[k]
        tabb[(size_t)(kp + 1) * 130 + 65 + dim] = basen + vn[e];   // prefNeg[k+1]
    }
    if (t == 0) {
        tabb[(size_t)2048 * 130 + dim] = 0.f;        // sufPos[2048]
        tabb[65 + dim] = 0.f;                        // prefNeg[0]
    }
}

// ---------------- kernel 5: per-row output (sortedD staged in smem) ----------------
__global__ void outK(const float* __restrict__ battn, float* __restrict__ out) {
    __shared__ float sd[NN];
    const int b = blockIdx.x >> 8;                     // 256 blocks per batch
    const int rowInB = ((blockIdx.x & 255) << 3) + (threadIdx.x >> 5);
    const int row = b * NN + rowInB;
    const int lane = threadIdx.x & 31;

    const float4* src = (const float4*)(g_sortedD + b * NN);
    float4* dst = (float4*)sd;
    for (int i = threadIdx.x; i < NN / 4; i += 256) dst[i] = src[i];
    __syncthreads();

    const float si = g_s[row] + *battn;
    const float tt = -si;    // d_j >= tt -> positive branch
    int lo = 0, hi = NN;
    while (lo < hi) {
        const int mid = (lo + hi) >> 1;
        if (sd[mid] < tt) lo = mid + 1; else hi = mid;
    }

    const float* tb = g_tab + ((size_t)b * 2049 + lo) * 130;
    const float P = __expf(si);
    const float Q = __expf(NEG_SLOPE * si);
    const float den = fmaf(P, tb[64], Q * tb[129]);
    const float inv = 1.0f / den;

    float* orow = out + (size_t)row * OUTD;
#pragma unroll
    for (int d0 = 0; d0 < 2; d0++) {
        const int d = lane + d0 * 32;
        const float num = fmaf(P, tb[d], Q * tb[65 + d]);
        const float o = num * inv;
        orow[d] = (o > 0.f) ? o : expm1f(o);   // ELU (alpha=1)
    }
}

// ---------------- launch ----------------
extern "C" void kernel_launch(void* const* d_in, const int* in_sizes, int n_in,
                              void* d_out, int out_size) {
    const float* h     = (const float*)d_in[0];
    const float* W     = (const float*)d_in[1];
    const float* bfc   = (const float*)d_in[2];
    const float* asrc  = (const float*)d_in[3];
    const float* adst  = (const float*)d_in[4];
    const float* battn = (const float*)d_in[5];
    float* out = (float*)d_out;

    cudaFuncSetAttribute(projectK, cudaFuncAttributeMaxDynamicSharedMemorySize, 64 * 1024);

    projectK<<<(BB * NN) / 64, 256, 64 * 1024>>>(h, W, bfc);
    sdK<<<(BB * NN * 32) / 1024, 1024>>>(asrc, adst);
    sortK<<<BB, 1024>>>();
    scanK<<<BB * 65, 256>>>();
    outK<<<(BB * NN) / 8, 256>>>(battn, out);
}